// round 1
// baseline (speedup 1.0000x reference)
#include <cuda_runtime.h>
#include <cuda_bf16.h>
#include <cstddef>

// Problem constants (fixed by setup_inputs)
#define BATCH 2
#define LSEQ  2048
#define DIM   512
#define NHEAD 8
#define HDIM  64
#define EPSV  1e-8f

// Scratch: X = C * P, Y = B / D, laid out [b][h][i][d] (row stride HDIM)
__device__ float g_X[BATCH * LSEQ * DIM];
__device__ float g_Y[BATCH * LSEQ * DIM];

// ---------------------------------------------------------------------------
// Kernel 1: sequential cumprod scan per (b, channel); emits X and Y.
// 1024 independent chains; loads are coalesced across the warp (consecutive
// channels), the multiplicative chain is the only serial dependency (FMUL lat 4).
// ---------------------------------------------------------------------------
__global__ void precompute_kernel(const float* __restrict__ Bp,
                                  const float* __restrict__ Cp,
                                  const float* __restrict__ Sp) {
    int tid = blockIdx.x * blockDim.x + threadIdx.x;   // 0..1023
    if (tid >= BATCH * DIM) return;
    int b  = tid >> 9;          // / DIM
    int c  = tid & (DIM - 1);
    int h  = c >> 6;            // / HDIM
    int dd = c & (HDIM - 1);

    size_t inBase  = (size_t)b * LSEQ * DIM + c;
    size_t outBase = ((size_t)(b * NHEAD + h) * LSEQ) * HDIM + dd;

    float q = 1.0f;  // q at step i holds cum_A[i-1] (cum_A[0] := 1)
    // i = 0 special case: P=1, D=1 (no eps), no q update
    {
        float bv = Bp[inBase];
        float cv = Cp[inBase];
        g_X[outBase] = cv;      // C * 1
        g_Y[outBase] = bv;      // B / 1
    }
    #pragma unroll 4
    for (int i = 1; i < LSEQ; ++i) {
        float a  = Sp[inBase + (size_t)i * DIM];
        float bv = Bp[inBase + (size_t)i * DIM];
        float cv = Cp[inBase + (size_t)i * DIM];
        g_X[outBase + (size_t)i * HDIM] = cv * q;
        g_Y[outBase + (size_t)i * HDIM] = bv / (q + EPSV);
        q *= a;                 // cum_A[i] = cum_A[i-1] * A_i
    }
}

// ---------------------------------------------------------------------------
// Kernel 2: batched triangular GEMM  T = X @ Y^T  (strict lower), zeros
// elsewhere. 128x128 tile, 256 threads, 8x8 microtile (split-4 mapping so all
// smem fragment reads are conflict-free LDS.128).
// ---------------------------------------------------------------------------
#define BK 32
#define SMSTRIDE 132   // 128 + 4 pad: keeps float4 alignment, breaks store conflicts

__global__ __launch_bounds__(256, 2)
void gemm_kernel(float* __restrict__ out) {
    const int bh = blockIdx.z;          // 0..15
    const int ti = blockIdx.y;          // row tile
    const int tj = blockIdx.x;          // col tile
    const int tid = threadIdx.x;
    const int tx = tid & 15;
    const int ty = tid >> 4;
    const int iBase = ti * 128;
    const int jBase = tj * 128;
    float* outM = out + (size_t)bh * LSEQ * LSEQ;

    if (tj > ti) {
        // strictly upper tile: pure zero fill (output is poisoned otherwise)
        float4 z = make_float4(0.f, 0.f, 0.f, 0.f);
        #pragma unroll
        for (int r = 0; r < 8; ++r) {
            int gi = iBase + ((r < 4) ? (ty * 4 + r) : (64 + ty * 4 + r - 4));
            float4* p = (float4*)(outM + (size_t)gi * LSEQ + jBase);
            p[tx]      = z;
            p[16 + tx] = z;
        }
        return;
    }

    __shared__ float As[BK * SMSTRIDE];
    __shared__ float Bs[BK * SMSTRIDE];

    const float* X = g_X + (size_t)bh * LSEQ * HDIM;
    const float* Y = g_Y + (size_t)bh * LSEQ * HDIM;

    float acc[8][8];
    #pragma unroll
    for (int r = 0; r < 8; ++r)
        #pragma unroll
        for (int c = 0; c < 8; ++c) acc[r][c] = 0.f;

    for (int kt = 0; kt < HDIM; kt += BK) {
        // Global -> smem (transposed): As[k][i], Bs[k][j]
        #pragma unroll
        for (int t = 0; t < 4; ++t) {
            int idx = tid + t * 256;        // 0..1023
            int row = idx >> 3;             // 0..127
            int kq  = idx & 7;              // float4 index within 32-wide K slab
            float4 v = *(const float4*)(X + (size_t)(iBase + row) * HDIM + kt + kq * 4);
            As[(kq * 4 + 0) * SMSTRIDE + row] = v.x;
            As[(kq * 4 + 1) * SMSTRIDE + row] = v.y;
            As[(kq * 4 + 2) * SMSTRIDE + row] = v.z;
            As[(kq * 4 + 3) * SMSTRIDE + row] = v.w;
            float4 w = *(const float4*)(Y + (size_t)(jBase + row) * HDIM + kt + kq * 4);
            Bs[(kq * 4 + 0) * SMSTRIDE + row] = w.x;
            Bs[(kq * 4 + 1) * SMSTRIDE + row] = w.y;
            Bs[(kq * 4 + 2) * SMSTRIDE + row] = w.z;
            Bs[(kq * 4 + 3) * SMSTRIDE + row] = w.w;
        }
        __syncthreads();

        #pragma unroll
        for (int k = 0; k < BK; ++k) {
            float4 a0 = *(const float4*)&As[k * SMSTRIDE + ty * 4];
            float4 a1 = *(const float4*)&As[k * SMSTRIDE + 64 + ty * 4];
            float4 b0 = *(const float4*)&Bs[k * SMSTRIDE + tx * 4];
            float4 b1 = *(const float4*)&Bs[k * SMSTRIDE + 64 + tx * 4];
            float ar[8] = {a0.x, a0.y, a0.z, a0.w, a1.x, a1.y, a1.z, a1.w};
            float br[8] = {b0.x, b0.y, b0.z, b0.w, b1.x, b1.y, b1.z, b1.w};
            #pragma unroll
            for (int r = 0; r < 8; ++r)
                #pragma unroll
                for (int c = 0; c < 8; ++c)
                    acc[r][c] += ar[r] * br[c];
        }
        __syncthreads();
    }

    const bool diagTile = (ti == tj);
    #pragma unroll
    for (int r = 0; r < 8; ++r) {
        int gi = iBase + ((r < 4) ? (ty * 4 + r) : (64 + ty * 4 + r - 4));
        float* rowP = outM + (size_t)gi * LSEQ;
        #pragma unroll
        for (int half = 0; half < 2; ++half) {
            int gj0 = jBase + half * 64 + tx * 4;
            float4 v;
            v.x = acc[r][half * 4 + 0];
            v.y = acc[r][half * 4 + 1];
            v.z = acc[r][half * 4 + 2];
            v.w = acc[r][half * 4 + 3];
            if (diagTile) {
                // strict lower only; diagonal (j==i) left 0, fixed by diag_kernel
                v.x = (gj0 + 0 < gi) ? v.x : 0.f;
                v.y = (gj0 + 1 < gi) ? v.y : 0.f;
                v.z = (gj0 + 2 < gi) ? v.z : 0.f;
                v.w = (gj0 + 3 < gi) ? v.w : 0.f;
            }
            *(float4*)(rowP + gj0) = v;
        }
    }
}

// ---------------------------------------------------------------------------
// Kernel 3: diagonal T_ii = C_i . B_i  (one warp per (b,h,i))
// ---------------------------------------------------------------------------
__global__ void diag_kernel(const float* __restrict__ Bp,
                            const float* __restrict__ Cp,
                            float* __restrict__ out) {
    int warpId = (blockIdx.x * blockDim.x + threadIdx.x) >> 5;
    int lane = threadIdx.x & 31;
    if (warpId >= BATCH * NHEAD * LSEQ) return;
    int b   = warpId >> 14;                 // / (NHEAD*LSEQ)
    int rem = warpId & (NHEAD * LSEQ - 1);
    int h   = rem >> 11;                    // / LSEQ
    int i   = rem & (LSEQ - 1);
    size_t base = ((size_t)b * LSEQ + i) * DIM + h * HDIM + lane;
    float s = Cp[base] * Bp[base] + Cp[base + 32] * Bp[base + 32];
    #pragma unroll
    for (int off = 16; off; off >>= 1)
        s += __shfl_down_sync(0xffffffffu, s, off);
    if (lane == 0)
        out[(((size_t)(b * NHEAD + h) * LSEQ) + i) * LSEQ + i] = s;
}

// ---------------------------------------------------------------------------
extern "C" void kernel_launch(void* const* d_in, const int* in_sizes, int n_in,
                              void* d_out, int out_size) {
    (void)in_sizes; (void)n_in; (void)out_size;
    const float* B = (const float*)d_in[0];
    const float* C = (const float*)d_in[1];
    const float* S = (const float*)d_in[2];
    float* out = (float*)d_out;

    // 1) scan -> X, Y
    precompute_kernel<<<8, 128>>>(B, C, S);

    // 2) triangular batched GEMM (writes the full 256 MB output)
    dim3 grid(LSEQ / 128, LSEQ / 128, BATCH * NHEAD);
    gemm_kernel<<<grid, 256>>>(out);

    // 3) diagonal fixup
    int nWarps = BATCH * NHEAD * LSEQ;              // 32768
    diag_kernel<<<(nWarps * 32) / 256, 256>>>(B, C, out);
}